// round 15
// baseline (speedup 1.0000x reference)
#include <cuda_runtime.h>
#include <cuda_fp16.h>
#include <math.h>
#include <stdint.h>

// ===========================================================================
// Geometry: plane width 44 (w pad 2+2), height 44 rows (h pad 2+2), dz 44.
// Flattened row n = ny*44 + wx. Tap (kd,kh,kw): row offset kh*44+kw, plane d+kd.
// xp[b][dz][n][ci], ci contiguous (128B rows).
// ===========================================================================
#define WPLANE 44
#define NPLANE 1980          // 44*45: 44*44=1936 valid+pad rows, +44 overrun
#define NVALID 1760          // 40*44
#define A_ROWS 436           // 256 + 4*44 + 4

__device__ __align__(128) __half g_xp[2ull * 44 * NPLANE * 64];
__device__ __align__(128) __half g_wh[125 * 144 * 64];   // [t][co][ci], t=(kd*5+kh)*5+kw

__device__ __forceinline__ float sus_f(float v) {
    return v > 0.f ? expf(-1.f / v) : 0.f;
}

// ===========================================================================
// Fused prep kernel. Linear grid of 3960 + 125 blocks:
//   bid < 3960 : zero/fill one (ny,dz,b) row-group of g_xp
//   bid >= 3960: build 256 (u,w) entries of one tap's g_wh
// ===========================================================================
__global__ void prep_kernel(const float* __restrict__ x,
                            const float* __restrict__ wtp,
                            const float* __restrict__ wsc0,
                            const float* __restrict__ wsc1) {
    int bid = blockIdx.x;
    int tid = threadIdx.x;

    if (bid < 3960) {
        // ---------------- fill g_xp ----------------
        int ny = bid % 45;
        int dz = (bid / 45) % 44;
        int b  = bid / 1980;
        bool interior = (dz >= 2 && dz < 42 && ny >= 2 && ny < 42);
        size_t rowbase = ((size_t)(b * 44 + dz) * NPLANE + (size_t)ny * WPLANE) * 64;

        if (!interior) {
            float4* dst = (float4*)(g_xp + rowbase);
            float4 z = make_float4(0.f, 0.f, 0.f, 0.f);
            for (int i = tid; i < 44 * 64 / 8; i += 256) dst[i] = z;
            return;
        }

        __shared__ float sm[40 * 65];
        int d = dz - 2, h = ny - 2;
        {
            const float* cbase = x + (size_t)b * 4096000 + d * 1600 + h * 40;
            int ci = tid / 40, w = tid - ci * 40;   // one div at entry only
#pragma unroll
            for (int k = 0; k < 10; k++) {
                sm[w * 65 + ci] = cbase[(size_t)ci * 64000 + w];
                ci += 6;
                w += 16;
                if (w >= 40) { w -= 40; ci++; }
            }
        }
        // zero pad columns w in {0,1,42,43}
        {
            float4* dst = (float4*)(g_xp + rowbase);
            float4 z = make_float4(0.f, 0.f, 0.f, 0.f);
            for (int i = tid; i < 32; i += 256) {
                int f4 = (i < 16) ? i : (336 + (i - 16));
                dst[f4] = z;
            }
        }
        __syncthreads();
#pragma unroll
        for (int k = 0; k < 10; k++) {
            int j = tid + k * 256;
            int w = j >> 6, ci = j & 63;
            g_xp[rowbase + (size_t)(w + 2) * 64 + ci] = __float2half(sm[w * 65 + ci]);
        }
        return;
    }

    // ---------------- build g_wh ----------------
    int t  = bid - 3960;        // 0..124
    int uw = tid;               // 0..255
    int u  = uw >> 4;
    int w  = uw & 15;

    int xi = t / 25, yi = (t / 5) % 5, zi = t % 5;
    float rx = -1.f + 0.5f * xi;
    float ry = -1.f + 0.5f * yi;
    float rz = -1.f + 0.5f * zi;
    float d  = sqrtf(rx * rx + ry * ry + rz * rz);

    const float EC = 1.14136f * expf(2.0f);
    float wv[7];
#pragma unroll
    for (int i = 0; i < 7; i++) wv[i] = 0.f;
#pragma unroll
    for (int r = 0; r < 5; r++) {
        float val  = (float)(r + 1) * (1.f / 6.f);
        float diff = (d - val) * 6.f;
        float e    = EC * sus_f(diff + 1.f) * sus_f(1.f - diff);
        if (e != 0.f) {
#pragma unroll
            for (int i = 0; i < 7; i++)
                wv[i] += e * wtp[r * 1792 + i * 256 + u * 16 + w];
        }
    }
    const float invS = 0.089442719099991587f;  // 1/5^1.5
#pragma unroll
    for (int i = 0; i < 7; i++) wv[i] *= invS;

    float n  = fmaxf(d, 1e-12f);
    float ux = rx / n, uy = ry / n, uz = rz / n;
    const float SQ3 = 1.7320508075688772f;
    const float SQ5 = 2.2360679774997896f;
    float sh1[3] = {SQ3 * ux, SQ3 * uy, SQ3 * uz};
    float sh2[5] = {SQ5 * SQ3 * ux * uz,
                    SQ5 * SQ3 * ux * uy,
                    SQ5 * (uy * uy - 0.5f * (ux * ux + uz * uz)),
                    SQ5 * SQ3 * uy * uz,
                    SQ5 * 0.5f * SQ3 * (uz * uz - ux * ux)};

    float C[3][3][5];
#pragma unroll
    for (int i = 0; i < 3; i++)
#pragma unroll
        for (int j = 0; j < 3; j++)
#pragma unroll
            for (int k = 0; k < 5; k++) C[i][j][k] = 0.f;
    {
        float s = sqrtf(2.f / 15.f);
        float h = 0.5f * sqrtf(3.f) * s;
        C[0][2][0] = h;  C[2][0][0] = h;
        C[0][1][1] = h;  C[1][0][1] = h;
        C[0][0][2] = -0.5f * s;  C[1][1][2] = s;  C[2][2][2] = -0.5f * s;
        C[1][2][3] = h;  C[2][1][3] = h;
        C[0][0][4] = -h; C[2][2][4] = h;
    }

    const float PW0 = 0.17677669529663687f;
    const float PW1 = 0.25f;
    const float PW2 = 0.39528470752104744f;
    const float F   = 0.1f;

    __half* wt = g_wh + (size_t)t * 144 * 64;
#define WRW(co, ci, v) wt[(size_t)(co) * 64 + (ci)] = __float2half(v)

    {
        float v = F * PW0 * wv[0];
        if (t == 62) v += 0.25f * wsc0[u * 16 + w];
        WRW(w, u, v);
    }
#pragma unroll
    for (int k = 0; k < 3; k++)
        WRW(16 + 3 * w + k, u, F * (PW1 / SQ3) * sh1[k] * wv[1]);
#pragma unroll
    for (int k = 0; k < 5; k++)
        WRW(64 + 5 * w + k, u, F * (PW2 / SQ5) * sh2[k] * wv[2]);

#pragma unroll
    for (int i = 0; i < 3; i++) {
        int ci = 16 + 3 * u + i;
        WRW(w, ci, F * (PW0 / SQ3) * sh1[i] * wv[4]);
#pragma unroll
        for (int k = 0; k < 3; k++) {
            float t2 = 0.f;
#pragma unroll
            for (int j = 0; j < 5; j++) t2 += C[i][k][j] * sh2[j];
            float v = (i == k ? (PW1 / SQ3) * wv[3] : 0.f) + PW1 * t2 * wv[6];
            v *= F;
            if (t == 62 && i == k) v += 0.25f * wsc1[u * 16 + w];
            WRW(16 + 3 * w + k, ci, v);
        }
#pragma unroll
        for (int k = 0; k < 5; k++) {
            float t3 = 0.f;
#pragma unroll
            for (int j = 0; j < 3; j++) t3 += C[i][j][k] * sh1[j];
            WRW(64 + 5 * w + k, ci, F * PW2 * t3 * wv[5]);
        }
    }
#undef WRW
}

// ===========================================================================
// Main conv: implicit GEMM on mma.sync (HMMA), fp16 single pass.
// Block: 256 voxels x 144 co, 8 warps (warp tile 64x72).
// Global windows of 2 taps (barrier every 2 taps). B in a 4-deep ring;
// A double-buffered per kd, restaged inside windows {0,13,25,38}.
// Fragments double-buffered across ks and across taps within a window.
// Epilogue: acc staged to SMEM [co][m] then stored as coalesced float4.
// SMEM rows 144B stride (conflict-free ldmatrix).
// ===========================================================================
#define A_BYTES (A_ROWS * 144)             // 62784
#define B_BYTES (144 * 144)                // 20736
#define SM_A    0
#define SM_B    (2 * A_BYTES)              // 125568
#define SMEM_TOTAL (SM_B + 4 * B_BYTES)    // 208512 (<= 232448)
#define EPI_STRIDE 260                     // floats per co row in epilogue smem

__device__ __forceinline__ uint32_t smem_u32(const void* p) {
    uint32_t a;
    asm("{ .reg .u64 t; cvta.to.shared.u64 t, %1; cvt.u32.u64 %0, t; }" : "=r"(a) : "l"(p));
    return a;
}
__device__ __forceinline__ void cpa16(uint32_t dst, const void* src) {
    asm volatile("cp.async.cg.shared.global [%0], [%1], 16;" :: "r"(dst), "l"(src));
}
__device__ __forceinline__ void cpa_commit() {
    asm volatile("cp.async.commit_group;" ::: "memory");
}
__device__ __forceinline__ void cpa_wait0() {
    asm volatile("cp.async.wait_group 0;" ::: "memory");
}
__device__ __forceinline__ void ldsm4(uint32_t* r, uint32_t addr) {
    asm volatile("ldmatrix.sync.aligned.m8n8.x4.shared.b16 {%0,%1,%2,%3}, [%4];"
                 : "=r"(r[0]), "=r"(r[1]), "=r"(r[2]), "=r"(r[3]) : "r"(addr));
}
__device__ __forceinline__ void ldsm2(uint32_t* r, uint32_t addr) {
    asm volatile("ldmatrix.sync.aligned.m8n8.x2.shared.b16 {%0,%1}, [%2];"
                 : "=r"(r[0]), "=r"(r[1]) : "r"(addr));
}
__device__ __forceinline__ void mma16816(float* d, const uint32_t* a, const uint32_t* bq) {
    asm volatile(
        "mma.sync.aligned.m16n8k16.row.col.f32.f16.f16.f32 "
        "{%0,%1,%2,%3}, {%4,%5,%6,%7}, {%8,%9}, {%0,%1,%2,%3};"
        : "+f"(d[0]), "+f"(d[1]), "+f"(d[2]), "+f"(d[3])
        : "r"(a[0]), "r"(a[1]), "r"(a[2]), "r"(a[3]), "r"(bq[0]), "r"(bq[1]));
}

__global__ void __launch_bounds__(256, 1)
conv_mma_kernel(float* __restrict__ out) {
    extern __shared__ char smem[];
    uint32_t sb = smem_u32(smem);
    const int tid  = threadIdx.x;
    const int lane = tid & 31;
    const int wid  = tid >> 5;
    const int mw   = wid & 3;     // M quarter (64 voxels)
    const int nw   = wid >> 2;    // N half (72 co)

    const int d = blockIdx.y;
    const int b = blockIdx.z;
    const int n0 = blockIdx.x * 256;

    // ---- staging ----
    auto stageA = [&](int kd) {
        uint32_t base = sb + SM_A + (uint32_t)(kd & 1) * A_BYTES;
        const __half* src0 = g_xp + ((size_t)(b * 44 + d + kd) * NPLANE + n0) * 64;
        for (int i = tid; i < A_ROWS * 8; i += 256) {
            int r = i >> 3, c = i & 7;
            cpa16(base + r * 144 + c * 16, src0 + (size_t)r * 64 + c * 8);
        }
    };
    auto stageB = [&](int t) {
        uint32_t base = sb + SM_B + (uint32_t)(t & 3) * B_BYTES;
        const __half* src0 = g_wh + (size_t)t * 144 * 64;
        for (int i = tid; i < 144 * 8; i += 256) {
            int r = i >> 3, c = i & 7;
            cpa16(base + r * 144 + c * 16, src0 + (size_t)r * 64 + c * 8);
        }
    };

    // prologue: A(0) + B(0,1), full drain
    stageA(0);
    stageB(0); stageB(1);
    cpa_commit();
    cpa_wait0();
    __syncthreads();

    float acc[4][9][4];
#pragma unroll
    for (int mt = 0; mt < 4; mt++)
#pragma unroll
        for (int nt = 0; nt < 9; nt++)
#pragma unroll
            for (int q = 0; q < 4; q++) acc[mt][nt][q] = 0.f;

    const uint32_t aLaneOff = (uint32_t)((mw * 64 + (lane & 15)) * 144 + (lane >> 4) * 16);
    const uint32_t bOff4 = (uint32_t)((nw * 72 + ((lane >> 4) << 3) + (lane & 7)) * 144 +
                                      ((lane >> 3) & 1) * 16);
    const uint32_t bOff2 = (uint32_t)((nw * 72 + 64 + (lane & 7)) * 144 +
                                      ((lane >> 3) & 1) * 16);

    // fragment double buffers
    uint32_t aF[2][4][4];
    uint32_t bF[2][9][2];

    auto loadFrags = [&](uint32_t aTap, uint32_t bBase, int ks, int buf) {
#pragma unroll
        for (int mt = 0; mt < 4; mt++)
            ldsm4(aF[buf][mt], aTap + mt * (16 * 144) + ks * 32);
#pragma unroll
        for (int nt = 0; nt < 4; nt++) {
            uint32_t r4[4];
            ldsm4(r4, bBase + bOff4 + nt * (16 * 144) + ks * 32);
            bF[buf][2 * nt][0] = r4[0]; bF[buf][2 * nt][1] = r4[1];
            bF[buf][2 * nt + 1][0] = r4[2]; bF[buf][2 * nt + 1][1] = r4[3];
        }
        ldsm2(bF[buf][8], bBase + bOff2 + ks * 32);
    };
    auto tapAddr = [&](int t) -> uint32_t {
        int kd = t / 25, j = t - kd * 25;
        int kh = j / 5, kw = j - kh * 5;
        return sb + SM_A + (uint32_t)(kd & 1) * A_BYTES + aLaneOff +
               (uint32_t)((kh * WPLANE + kw) * 144);
    };
    auto bAddr = [&](int t) -> uint32_t {
        return sb + SM_B + (uint32_t)(t & 3) * B_BYTES;
    };

    // global windows of 2 taps: w=0..61 cover taps 0..123; w=62 is tap 124
#pragma unroll 1
    for (int w = 0; w < 63; w++) {
        const int t0 = 2 * w;
        const int ws = (t0 == 124) ? 1 : 2;

        if (t0 + 2 <= 124) stageB(t0 + 2);
        if (t0 + 3 <= 124) stageB(t0 + 3);
        if      (w == 0)  stageA(1);
        else if (w == 13) stageA(2);
        else if (w == 25) stageA(3);
        else if (w == 38) stageA(4);
        cpa_commit();

        uint32_t aTapC  = tapAddr(t0);
        uint32_t bBaseC = bAddr(t0);
        loadFrags(aTapC, bBaseC, 0, 0);
#pragma unroll 1
        for (int jj = 0; jj < ws; jj++) {
            int tn = t0 + jj + 1;
            uint32_t aTapN  = tapAddr(tn <= 124 ? tn : 124);
            uint32_t bBaseN = bAddr(tn);

#pragma unroll
            for (int ks = 0; ks < 4; ks++) {
                int cur = ks & 1, nxt = cur ^ 1;
                if (ks < 3)            loadFrags(aTapC, bBaseC, ks + 1, nxt);
                else if (jj + 1 < ws)  loadFrags(aTapN, bBaseN, 0, nxt);
#pragma unroll
                for (int mt = 0; mt < 4; mt++)
#pragma unroll
                    for (int nt = 0; nt < 9; nt++)
                        mma16816(acc[mt][nt], aF[cur][mt], bF[cur][nt]);
            }
            aTapC = aTapN; bBaseC = bBaseN;
        }

        cpa_wait0();
        __syncthreads();    // window boundary (final one frees smem for epilogue)
    }

    // ---- epilogue: stage acc to SMEM [co][m] then coalesced float4 stores ----
    float* sOut = (float*)smem;   // 144 * EPI_STRIDE * 4 = 149760 B <= SMEM_TOTAL
#pragma unroll
    for (int mt = 0; mt < 4; mt++) {
        int m0 = mw * 64 + mt * 16 + (lane >> 2);
#pragma unroll
        for (int nt = 0; nt < 9; nt++) {
            int co = nw * 72 + nt * 8 + (lane & 3) * 2;
            sOut[co * EPI_STRIDE + m0]            = acc[mt][nt][0];
            sOut[(co + 1) * EPI_STRIDE + m0]      = acc[mt][nt][1];
            sOut[co * EPI_STRIDE + m0 + 8]        = acc[mt][nt][2];
            sOut[(co + 1) * EPI_STRIDE + m0 + 8]  = acc[mt][nt][3];
        }
    }
    __syncthreads();

    const size_t ob = (size_t)b * 144 * 64000 + (size_t)d * 1600;
#pragma unroll 1
    for (int i = tid; i < 144 * 64; i += 256) {
        int co = i >> 6;
        int m  = (i & 63) * 4;
        int n  = n0 + m;
        int h  = n / WPLANE, w = n - h * WPLANE;   // w % 4 == 0
        if (w < 40 && n < NVALID) {
            float4 v = *(float4*)&sOut[co * EPI_STRIDE + m];
            *(float4*)&out[ob + (size_t)co * 64000 + h * 40 + w] = v;
        }
    }
}

// ===========================================================================
extern "C" void kernel_launch(void* const* d_in, const int* in_sizes, int n_in,
                              void* d_out, int out_size) {
    const float* x    = (const float*)d_in[0];
    const float* wsc0 = (const float*)d_in[1];
    const float* wsc1 = (const float*)d_in[2];
    const float* wtp  = (const float*)d_in[3];
    float* out = (float*)d_out;

    prep_kernel<<<3960 + 125, 256>>>(x, wtp, wsc0, wsc1);

    cudaFuncSetAttribute(conv_mma_kernel,
                         cudaFuncAttributeMaxDynamicSharedMemorySize, SMEM_TOTAL);
    conv_mma_kernel<<<dim3(7, 40, 2), 256, SMEM_TOTAL>>>(out);
}

// round 16
// speedup vs baseline: 1.0104x; 1.0104x over previous
#include <cuda_runtime.h>
#include <cuda_fp16.h>
#include <math.h>
#include <stdint.h>

// ===========================================================================
// Geometry: plane width 44 (w pad 2+2), height 44 rows (h pad 2+2), dz 44.
// Flattened row n = ny*44 + wx. Tap (kd,kh,kw): row offset kh*44+kw, plane d+kd.
// xp[b][dz][n][ci], ci contiguous (128B rows).
// ===========================================================================
#define WPLANE 44
#define NPLANE 1980          // 44*45: 44*44=1936 valid+pad rows, +44 overrun
#define NVALID 1760          // 40*44
#define A_ROWS 436           // 256 + 4*44 + 4

__device__ __align__(128) __half g_xp[2ull * 44 * NPLANE * 64];
__device__ __align__(128) __half g_wh[125 * 144 * 64];   // [t][co][ci], t=(kd*5+kh)*5+kw

__device__ __forceinline__ float sus_f(float v) {
    return v > 0.f ? expf(-1.f / v) : 0.f;
}

// ===========================================================================
// Builder: writes g_wh[t][co][ci] fp16 directly. 0.1 conv scale folded,
// self-connection folded into center tap t=62.
// ===========================================================================
__global__ void build_weights_kernel(const float* __restrict__ wtp,
                                     const float* __restrict__ wsc0,
                                     const float* __restrict__ wsc1) {
    int id = blockIdx.x * blockDim.x + threadIdx.x;
    if (id >= 32000) return;
    int t  = id >> 8;
    int uw = id & 255;
    int u  = uw >> 4;
    int w  = uw & 15;

    int xi = t / 25, yi = (t / 5) % 5, zi = t % 5;
    float rx = -1.f + 0.5f * xi;
    float ry = -1.f + 0.5f * yi;
    float rz = -1.f + 0.5f * zi;
    float d  = sqrtf(rx * rx + ry * ry + rz * rz);

    const float EC = 1.14136f * expf(2.0f);
    float wv[7];
#pragma unroll
    for (int i = 0; i < 7; i++) wv[i] = 0.f;
#pragma unroll
    for (int r = 0; r < 5; r++) {
        float val  = (float)(r + 1) * (1.f / 6.f);
        float diff = (d - val) * 6.f;
        float e    = EC * sus_f(diff + 1.f) * sus_f(1.f - diff);
        if (e != 0.f) {
#pragma unroll
            for (int i = 0; i < 7; i++)
                wv[i] += e * wtp[r * 1792 + i * 256 + u * 16 + w];
        }
    }
    const float invS = 0.089442719099991587f;  // 1/5^1.5
#pragma unroll
    for (int i = 0; i < 7; i++) wv[i] *= invS;

    float n  = fmaxf(d, 1e-12f);
    float ux = rx / n, uy = ry / n, uz = rz / n;
    const float SQ3 = 1.7320508075688772f;
    const float SQ5 = 2.2360679774997896f;
    float sh1[3] = {SQ3 * ux, SQ3 * uy, SQ3 * uz};
    float sh2[5] = {SQ5 * SQ3 * ux * uz,
                    SQ5 * SQ3 * ux * uy,
                    SQ5 * (uy * uy - 0.5f * (ux * ux + uz * uz)),
                    SQ5 * SQ3 * uy * uz,
                    SQ5 * 0.5f * SQ3 * (uz * uz - ux * ux)};

    float C[3][3][5];
#pragma unroll
    for (int i = 0; i < 3; i++)
#pragma unroll
        for (int j = 0; j < 3; j++)
#pragma unroll
            for (int k = 0; k < 5; k++) C[i][j][k] = 0.f;
    {
        float s = sqrtf(2.f / 15.f);
        float h = 0.5f * sqrtf(3.f) * s;
        C[0][2][0] = h;  C[2][0][0] = h;
        C[0][1][1] = h;  C[1][0][1] = h;
        C[0][0][2] = -0.5f * s;  C[1][1][2] = s;  C[2][2][2] = -0.5f * s;
        C[1][2][3] = h;  C[2][1][3] = h;
        C[0][0][4] = -h; C[2][2][4] = h;
    }

    const float PW0 = 0.17677669529663687f;
    const float PW1 = 0.25f;
    const float PW2 = 0.39528470752104744f;
    const float F   = 0.1f;

    __half* wt = g_wh + (size_t)t * 144 * 64;
#define WRW(co, ci, v) wt[(size_t)(co) * 64 + (ci)] = __float2half(v)

    {
        float v = F * PW0 * wv[0];
        if (t == 62) v += 0.25f * wsc0[u * 16 + w];
        WRW(w, u, v);
    }
#pragma unroll
    for (int k = 0; k < 3; k++)
        WRW(16 + 3 * w + k, u, F * (PW1 / SQ3) * sh1[k] * wv[1]);
#pragma unroll
    for (int k = 0; k < 5; k++)
        WRW(64 + 5 * w + k, u, F * (PW2 / SQ5) * sh2[k] * wv[2]);

#pragma unroll
    for (int i = 0; i < 3; i++) {
        int ci = 16 + 3 * u + i;
        WRW(w, ci, F * (PW0 / SQ3) * sh1[i] * wv[4]);
#pragma unroll
        for (int k = 0; k < 3; k++) {
            float t2 = 0.f;
#pragma unroll
            for (int j = 0; j < 5; j++) t2 += C[i][k][j] * sh2[j];
            float v = (i == k ? (PW1 / SQ3) * wv[3] : 0.f) + PW1 * t2 * wv[6];
            v *= F;
            if (t == 62 && i == k) v += 0.25f * wsc1[u * 16 + w];
            WRW(16 + 3 * w + k, ci, v);
        }
#pragma unroll
        for (int k = 0; k < 5; k++) {
            float t3 = 0.f;
#pragma unroll
            for (int j = 0; j < 3; j++) t3 += C[i][j][k] * sh1[j];
            WRW(64 + 5 * w + k, ci, F * PW2 * t3 * wv[5]);
        }
    }
#undef WRW
}

// ===========================================================================
// Fused zero+fill: grid (ny=45, dz=44, b=2), 256 threads.
// Vectorized 16B stores on the write-back path.
// ===========================================================================
__global__ void fill_xp_kernel(const float* __restrict__ x) {
    int ny = blockIdx.x, dz = blockIdx.y, b = blockIdx.z;
    int tid = threadIdx.x;
    bool interior = (dz >= 2 && dz < 42 && ny >= 2 && ny < 42);
    size_t rowbase = ((size_t)(b * 44 + dz) * NPLANE + (size_t)ny * WPLANE) * 64;

    if (!interior) {
        float4* dst = (float4*)(g_xp + rowbase);
        float4 z = make_float4(0.f, 0.f, 0.f, 0.f);
        for (int i = tid; i < 44 * 64 / 8; i += 256) dst[i] = z;
        return;
    }

    __shared__ float sm[40 * 65];
    int d = dz - 2, h = ny - 2;
    {
        const float* cbase = x + (size_t)b * 4096000 + d * 1600 + h * 40;
        int ci = tid / 40, w = tid - ci * 40;   // one div at entry only
#pragma unroll
        for (int k = 0; k < 10; k++) {
            sm[w * 65 + ci] = cbase[(size_t)ci * 64000 + w];
            ci += 6;
            w += 16;
            if (w >= 40) { w -= 40; ci++; }
        }
    }
    // zero pad columns w in {0,1,42,43}
    {
        float4* dst = (float4*)(g_xp + rowbase);
        float4 z = make_float4(0.f, 0.f, 0.f, 0.f);
        for (int i = tid; i < 32; i += 256) {
            int f4 = (i < 16) ? i : (336 + (i - 16));
            dst[f4] = z;
        }
    }
    __syncthreads();
    // write-back: 40 w-rows x 8 chunks of 8 ci (16B each) = 320 chunks
#pragma unroll
    for (int k = 0; k < 2; k++) {
        int chunk = tid + k * 256;
        if (chunk < 320) {
            int w  = chunk >> 3;
            int c8 = (chunk & 7) * 8;
            const float* s = &sm[w * 65 + c8];
            __half h8[8];
#pragma unroll
            for (int q = 0; q < 8; q++) h8[q] = __float2half(s[q]);
            *(uint4*)&g_xp[rowbase + (size_t)(w + 2) * 64 + c8] = *(uint4*)h8;
        }
    }
}

// ===========================================================================
// Main conv: implicit GEMM on mma.sync (HMMA), fp16 single pass.
// Block: 256 voxels x 144 co, 8 warps (warp tile 64x72).
// Global windows of 2 taps (barrier every 2 taps). B in a 4-deep ring;
// A double-buffered per kd, restaged inside windows {0,13,25,38}.
// Fragments double-buffered across ks and across taps within a window.
// Epilogue: acc staged to SMEM [co][m] then stored as coalesced float4.
// SMEM rows 144B stride (conflict-free ldmatrix).
// ===========================================================================
#define A_BYTES (A_ROWS * 144)             // 62784
#define B_BYTES (144 * 144)                // 20736
#define SM_A    0
#define SM_B    (2 * A_BYTES)              // 125568
#define SMEM_TOTAL (SM_B + 4 * B_BYTES)    // 208512 (<= 232448)
#define EPI_STRIDE 260                     // floats per co row in epilogue smem

__device__ __forceinline__ uint32_t smem_u32(const void* p) {
    uint32_t a;
    asm("{ .reg .u64 t; cvta.to.shared.u64 t, %1; cvt.u32.u64 %0, t; }" : "=r"(a) : "l"(p));
    return a;
}
__device__ __forceinline__ void cpa16(uint32_t dst, const void* src) {
    asm volatile("cp.async.cg.shared.global [%0], [%1], 16;" :: "r"(dst), "l"(src));
}
__device__ __forceinline__ void cpa_commit() {
    asm volatile("cp.async.commit_group;" ::: "memory");
}
__device__ __forceinline__ void cpa_wait0() {
    asm volatile("cp.async.wait_group 0;" ::: "memory");
}
__device__ __forceinline__ void ldsm4(uint32_t* r, uint32_t addr) {
    asm volatile("ldmatrix.sync.aligned.m8n8.x4.shared.b16 {%0,%1,%2,%3}, [%4];"
                 : "=r"(r[0]), "=r"(r[1]), "=r"(r[2]), "=r"(r[3]) : "r"(addr));
}
__device__ __forceinline__ void ldsm2(uint32_t* r, uint32_t addr) {
    asm volatile("ldmatrix.sync.aligned.m8n8.x2.shared.b16 {%0,%1}, [%2];"
                 : "=r"(r[0]), "=r"(r[1]) : "r"(addr));
}
__device__ __forceinline__ void mma16816(float* d, const uint32_t* a, const uint32_t* bq) {
    asm volatile(
        "mma.sync.aligned.m16n8k16.row.col.f32.f16.f16.f32 "
        "{%0,%1,%2,%3}, {%4,%5,%6,%7}, {%8,%9}, {%0,%1,%2,%3};"
        : "+f"(d[0]), "+f"(d[1]), "+f"(d[2]), "+f"(d[3])
        : "r"(a[0]), "r"(a[1]), "r"(a[2]), "r"(a[3]), "r"(bq[0]), "r"(bq[1]));
}

__global__ void __launch_bounds__(256, 1)
conv_mma_kernel(float* __restrict__ out) {
    extern __shared__ char smem[];
    uint32_t sb = smem_u32(smem);
    const int tid  = threadIdx.x;
    const int lane = tid & 31;
    const int wid  = tid >> 5;
    const int mw   = wid & 3;     // M quarter (64 voxels)
    const int nw   = wid >> 2;    // N half (72 co)

    const int d = blockIdx.y;
    const int b = blockIdx.z;
    const int n0 = blockIdx.x * 256;

    // ---- staging ----
    auto stageA = [&](int kd) {
        uint32_t base = sb + SM_A + (uint32_t)(kd & 1) * A_BYTES;
        const __half* src0 = g_xp + ((size_t)(b * 44 + d + kd) * NPLANE + n0) * 64;
        for (int i = tid; i < A_ROWS * 8; i += 256) {
            int r = i >> 3, c = i & 7;
            cpa16(base + r * 144 + c * 16, src0 + (size_t)r * 64 + c * 8);
        }
    };
    auto stageB = [&](int t) {
        uint32_t base = sb + SM_B + (uint32_t)(t & 3) * B_BYTES;
        const __half* src0 = g_wh + (size_t)t * 144 * 64;
        for (int i = tid; i < 144 * 8; i += 256) {
            int r = i >> 3, c = i & 7;
            cpa16(base + r * 144 + c * 16, src0 + (size_t)r * 64 + c * 8);
        }
    };

    // prologue: A(0) + B(0,1), full drain
    stageA(0);
    stageB(0); stageB(1);
    cpa_commit();
    cpa_wait0();
    __syncthreads();

    float acc[4][9][4];
#pragma unroll
    for (int mt = 0; mt < 4; mt++)
#pragma unroll
        for (int nt = 0; nt < 9; nt++)
#pragma unroll
            for (int q = 0; q < 4; q++) acc[mt][nt][q] = 0.f;

    const uint32_t aLaneOff = (uint32_t)((mw * 64 + (lane & 15)) * 144 + (lane >> 4) * 16);
    const uint32_t bOff4 = (uint32_t)((nw * 72 + ((lane >> 4) << 3) + (lane & 7)) * 144 +
                                      ((lane >> 3) & 1) * 16);
    const uint32_t bOff2 = (uint32_t)((nw * 72 + 64 + (lane & 7)) * 144 +
                                      ((lane >> 3) & 1) * 16);

    // fragment double buffers
    uint32_t aF[2][4][4];
    uint32_t bF[2][9][2];

    auto loadFrags = [&](uint32_t aTap, uint32_t bBase, int ks, int buf) {
#pragma unroll
        for (int mt = 0; mt < 4; mt++)
            ldsm4(aF[buf][mt], aTap + mt * (16 * 144) + ks * 32);
#pragma unroll
        for (int nt = 0; nt < 4; nt++) {
            uint32_t r4[4];
            ldsm4(r4, bBase + bOff4 + nt * (16 * 144) + ks * 32);
            bF[buf][2 * nt][0] = r4[0]; bF[buf][2 * nt][1] = r4[1];
            bF[buf][2 * nt + 1][0] = r4[2]; bF[buf][2 * nt + 1][1] = r4[3];
        }
        ldsm2(bF[buf][8], bBase + bOff2 + ks * 32);
    };
    auto tapAddr = [&](int t) -> uint32_t {
        int kd = t / 25, j = t - kd * 25;
        int kh = j / 5, kw = j - kh * 5;
        return sb + SM_A + (uint32_t)(kd & 1) * A_BYTES + aLaneOff +
               (uint32_t)((kh * WPLANE + kw) * 144);
    };
    auto bAddr = [&](int t) -> uint32_t {
        return sb + SM_B + (uint32_t)(t & 3) * B_BYTES;
    };

    // global windows of 2 taps: w=0..61 cover taps 0..123; w=62 is tap 124
#pragma unroll 1
    for (int w = 0; w < 63; w++) {
        const int t0 = 2 * w;
        const int ws = (t0 == 124) ? 1 : 2;

        if (t0 + 2 <= 124) stageB(t0 + 2);
        if (t0 + 3 <= 124) stageB(t0 + 3);
        if      (w == 0)  stageA(1);
        else if (w == 13) stageA(2);
        else if (w == 25) stageA(3);
        else if (w == 38) stageA(4);
        cpa_commit();

        uint32_t aTapC  = tapAddr(t0);
        uint32_t bBaseC = bAddr(t0);
        loadFrags(aTapC, bBaseC, 0, 0);
#pragma unroll 1
        for (int jj = 0; jj < ws; jj++) {
            int tn = t0 + jj + 1;
            uint32_t aTapN  = tapAddr(tn <= 124 ? tn : 124);
            uint32_t bBaseN = bAddr(tn);

#pragma unroll
            for (int ks = 0; ks < 4; ks++) {
                int cur = ks & 1, nxt = cur ^ 1;
                if (ks < 3)            loadFrags(aTapC, bBaseC, ks + 1, nxt);
                else if (jj + 1 < ws)  loadFrags(aTapN, bBaseN, 0, nxt);
#pragma unroll
                for (int mt = 0; mt < 4; mt++)
#pragma unroll
                    for (int nt = 0; nt < 9; nt++)
                        mma16816(acc[mt][nt], aF[cur][mt], bF[cur][nt]);
            }
            aTapC = aTapN; bBaseC = bBaseN;
        }

        cpa_wait0();
        __syncthreads();    // window boundary (final one frees smem for epilogue)
    }

    // ---- epilogue: stage acc to SMEM [co][m] then coalesced float4 stores ----
    float* sOut = (float*)smem;   // 144 * EPI_STRIDE * 4 = 149760 B <= SMEM_TOTAL
#pragma unroll
    for (int mt = 0; mt < 4; mt++) {
        int m0 = mw * 64 + mt * 16 + (lane >> 2);
#pragma unroll
        for (int nt = 0; nt < 9; nt++) {
            int co = nw * 72 + nt * 8 + (lane & 3) * 2;
            sOut[co * EPI_STRIDE + m0]            = acc[mt][nt][0];
            sOut[(co + 1) * EPI_STRIDE + m0]      = acc[mt][nt][1];
            sOut[co * EPI_STRIDE + m0 + 8]        = acc[mt][nt][2];
            sOut[(co + 1) * EPI_STRIDE + m0 + 8]  = acc[mt][nt][3];
        }
    }
    __syncthreads();

    const size_t ob = (size_t)b * 144 * 64000 + (size_t)d * 1600;
#pragma unroll 1
    for (int i = tid; i < 144 * 64; i += 256) {
        int co = i >> 6;
        int m  = (i & 63) * 4;
        int n  = n0 + m;
        int h  = n / WPLANE, w = n - h * WPLANE;   // w % 4 == 0
        if (w < 40 && n < NVALID) {
            float4 v = *(float4*)&sOut[co * EPI_STRIDE + m];
            *(float4*)&out[ob + (size_t)co * 64000 + h * 40 + w] = v;
        }
    }
}

// ===========================================================================
extern "C" void kernel_launch(void* const* d_in, const int* in_sizes, int n_in,
                              void* d_out, int out_size) {
    const float* x    = (const float*)d_in[0];
    const float* wsc0 = (const float*)d_in[1];
    const float* wsc1 = (const float*)d_in[2];
    const float* wtp  = (const float*)d_in[3];
    float* out = (float*)d_out;

    fill_xp_kernel<<<dim3(45, 44, 2), 256>>>(x);
    build_weights_kernel<<<125, 256>>>(wtp, wsc0, wsc1);

    cudaFuncSetAttribute(conv_mma_kernel,
                         cudaFuncAttributeMaxDynamicSharedMemorySize, SMEM_TOTAL);
    conv_mma_kernel<<<dim3(7, 40, 2), 256, SMEM_TOTAL>>>(out);
}

// round 17
// speedup vs baseline: 1.0169x; 1.0065x over previous
#include <cuda_runtime.h>
#include <cuda_fp16.h>
#include <math.h>
#include <stdint.h>

// ===========================================================================
// Geometry: plane width 44 (w pad 2+2), height 44 rows (h pad 2+2), dz 44.
// Flattened row n = ny*44 + wx. Tap (kd,kh,kw): row offset kh*44+kw, plane d+kd.
// xp[b][dz][n][ci], ci contiguous (128B rows).
// ===========================================================================
#define WPLANE 44
#define NPLANE 1980          // 44*45: 44*44=1936 valid+pad rows, +44 overrun
#define NVALID 1760          // 40*44
#define A_ROWS 436           // 256 + 4*44 + 4

__device__ __align__(128) __half g_xp[2ull * 44 * NPLANE * 64];
__device__ __align__(128) __half g_wh[125 * 144 * 64];   // [t][co][ci], t=(kd*5+kh)*5+kw

__device__ __forceinline__ float sus_f(float v) {
    return v > 0.f ? expf(-1.f / v) : 0.f;
}

// ===========================================================================
// Builder: one block per tap. Computes W(co,ci) into SMEM, then coalesced
// 16B copies to g_wh. 0.1 conv scale folded, self-connection folded into
// center tap t=62.
// ===========================================================================
__global__ void build_weights_kernel(const float* __restrict__ wtp,
                                     const float* __restrict__ wsc0,
                                     const float* __restrict__ wsc1) {
    __shared__ __half sw[144 * 64];
    int t   = blockIdx.x;     // 0..124
    int tid = threadIdx.x;    // 0..255
    int u   = tid >> 4;
    int w   = tid & 15;

    int xi = t / 25, yi = (t / 5) % 5, zi = t % 5;
    float rx = -1.f + 0.5f * xi;
    float ry = -1.f + 0.5f * yi;
    float rz = -1.f + 0.5f * zi;
    float d  = sqrtf(rx * rx + ry * ry + rz * rz);

    const float EC = 1.14136f * expf(2.0f);
    float wv[7];
#pragma unroll
    for (int i = 0; i < 7; i++) wv[i] = 0.f;
#pragma unroll
    for (int r = 0; r < 5; r++) {
        float val  = (float)(r + 1) * (1.f / 6.f);
        float diff = (d - val) * 6.f;
        float e    = EC * sus_f(diff + 1.f) * sus_f(1.f - diff);
        if (e != 0.f) {
#pragma unroll
            for (int i = 0; i < 7; i++)
                wv[i] += e * wtp[r * 1792 + i * 256 + u * 16 + w];
        }
    }
    const float invS = 0.089442719099991587f;  // 1/5^1.5
#pragma unroll
    for (int i = 0; i < 7; i++) wv[i] *= invS;

    float n  = fmaxf(d, 1e-12f);
    float ux = rx / n, uy = ry / n, uz = rz / n;
    const float SQ3 = 1.7320508075688772f;
    const float SQ5 = 2.2360679774997896f;
    float sh1[3] = {SQ3 * ux, SQ3 * uy, SQ3 * uz};
    float sh2[5] = {SQ5 * SQ3 * ux * uz,
                    SQ5 * SQ3 * ux * uy,
                    SQ5 * (uy * uy - 0.5f * (ux * ux + uz * uz)),
                    SQ5 * SQ3 * uy * uz,
                    SQ5 * 0.5f * SQ3 * (uz * uz - ux * ux)};

    float C[3][3][5];
#pragma unroll
    for (int i = 0; i < 3; i++)
#pragma unroll
        for (int j = 0; j < 3; j++)
#pragma unroll
            for (int k = 0; k < 5; k++) C[i][j][k] = 0.f;
    {
        float s = sqrtf(2.f / 15.f);
        float h = 0.5f * sqrtf(3.f) * s;
        C[0][2][0] = h;  C[2][0][0] = h;
        C[0][1][1] = h;  C[1][0][1] = h;
        C[0][0][2] = -0.5f * s;  C[1][1][2] = s;  C[2][2][2] = -0.5f * s;
        C[1][2][3] = h;  C[2][1][3] = h;
        C[0][0][4] = -h; C[2][2][4] = h;
    }

    const float PW0 = 0.17677669529663687f;
    const float PW1 = 0.25f;
    const float PW2 = 0.39528470752104744f;
    const float F   = 0.1f;

#define WRW(co, ci, v) sw[(co) * 64 + (ci)] = __float2half(v)

    {
        float v = F * PW0 * wv[0];
        if (t == 62) v += 0.25f * wsc0[u * 16 + w];
        WRW(w, u, v);
    }
#pragma unroll
    for (int k = 0; k < 3; k++)
        WRW(16 + 3 * w + k, u, F * (PW1 / SQ3) * sh1[k] * wv[1]);
#pragma unroll
    for (int k = 0; k < 5; k++)
        WRW(64 + 5 * w + k, u, F * (PW2 / SQ5) * sh2[k] * wv[2]);

#pragma unroll
    for (int i = 0; i < 3; i++) {
        int ci = 16 + 3 * u + i;
        WRW(w, ci, F * (PW0 / SQ3) * sh1[i] * wv[4]);
#pragma unroll
        for (int k = 0; k < 3; k++) {
            float t2 = 0.f;
#pragma unroll
            for (int j = 0; j < 5; j++) t2 += C[i][k][j] * sh2[j];
            float v = (i == k ? (PW1 / SQ3) * wv[3] : 0.f) + PW1 * t2 * wv[6];
            v *= F;
            if (t == 62 && i == k) v += 0.25f * wsc1[u * 16 + w];
            WRW(16 + 3 * w + k, ci, v);
        }
#pragma unroll
        for (int k = 0; k < 5; k++) {
            float t3 = 0.f;
#pragma unroll
            for (int j = 0; j < 3; j++) t3 += C[i][j][k] * sh1[j];
            WRW(64 + 5 * w + k, ci, F * PW2 * t3 * wv[5]);
        }
    }
#undef WRW

    __syncthreads();
    // coalesced copy out: 144*64 halves = 1152 uint4
    uint4* dst = (uint4*)(g_wh + (size_t)t * 144 * 64);
    const uint4* src = (const uint4*)sw;
#pragma unroll
    for (int k = 0; k < 5; k++) {
        int i = tid + k * 256;
        if (i < 1152) dst[i] = src[i];
    }
}

// ===========================================================================
// Fused zero+fill: grid (ny=45, dz=44, b=2), 256 threads.
// Vectorized 16B stores on the write-back path.
// ===========================================================================
__global__ void fill_xp_kernel(const float* __restrict__ x) {
    int ny = blockIdx.x, dz = blockIdx.y, b = blockIdx.z;
    int tid = threadIdx.x;
    bool interior = (dz >= 2 && dz < 42 && ny >= 2 && ny < 42);
    size_t rowbase = ((size_t)(b * 44 + dz) * NPLANE + (size_t)ny * WPLANE) * 64;

    if (!interior) {
        float4* dst = (float4*)(g_xp + rowbase);
        float4 z = make_float4(0.f, 0.f, 0.f, 0.f);
        for (int i = tid; i < 44 * 64 / 8; i += 256) dst[i] = z;
        return;
    }

    __shared__ float sm[40 * 65];
    int d = dz - 2, h = ny - 2;
    {
        const float* cbase = x + (size_t)b * 4096000 + d * 1600 + h * 40;
        int ci = tid / 40, w = tid - ci * 40;   // one div at entry only
#pragma unroll
        for (int k = 0; k < 10; k++) {
            sm[w * 65 + ci] = cbase[(size_t)ci * 64000 + w];
            ci += 6;
            w += 16;
            if (w >= 40) { w -= 40; ci++; }
        }
    }
    // zero pad columns w in {0,1,42,43}
    {
        float4* dst = (float4*)(g_xp + rowbase);
        float4 z = make_float4(0.f, 0.f, 0.f, 0.f);
        for (int i = tid; i < 32; i += 256) {
            int f4 = (i < 16) ? i : (336 + (i - 16));
            dst[f4] = z;
        }
    }
    __syncthreads();
    // write-back: 40 w-rows x 8 chunks of 8 ci (16B each) = 320 chunks
#pragma unroll
    for (int k = 0; k < 2; k++) {
        int chunk = tid + k * 256;
        if (chunk < 320) {
            int w  = chunk >> 3;
            int c8 = (chunk & 7) * 8;
            const float* s = &sm[w * 65 + c8];
            __half h8[8];
#pragma unroll
            for (int q = 0; q < 8; q++) h8[q] = __float2half(s[q]);
            *(uint4*)&g_xp[rowbase + (size_t)(w + 2) * 64 + c8] = *(uint4*)h8;
        }
    }
}

// ===========================================================================
// Main conv: implicit GEMM on mma.sync (HMMA), fp16 single pass.
// Block: 256 voxels x 144 co, 8 warps (warp tile 64x72).
// Global windows of 2 taps (barrier every 2 taps). B in a 4-deep ring;
// A double-buffered per kd, restaged inside windows {0,13,25,38}.
// Fragments double-buffered across ks and across taps within a window.
// Epilogue: acc staged to SMEM [co][m] then stored as coalesced float4.
// SMEM rows 144B stride (conflict-free ldmatrix).
// ===========================================================================
#define A_BYTES (A_ROWS * 144)             // 62784
#define B_BYTES (144 * 144)                // 20736
#define SM_A    0
#define SM_B    (2 * A_BYTES)              // 125568
#define SMEM_TOTAL (SM_B + 4 * B_BYTES)    // 208512 (<= 232448)
#define EPI_STRIDE 260                     // floats per co row in epilogue smem

__device__ __forceinline__ uint32_t smem_u32(const void* p) {
    uint32_t a;
    asm("{ .reg .u64 t; cvta.to.shared.u64 t, %1; cvt.u32.u64 %0, t; }" : "=r"(a) : "l"(p));
    return a;
}
__device__ __forceinline__ void cpa16(uint32_t dst, const void* src) {
    asm volatile("cp.async.cg.shared.global [%0], [%1], 16;" :: "r"(dst), "l"(src));
}
__device__ __forceinline__ void cpa_commit() {
    asm volatile("cp.async.commit_group;" ::: "memory");
}
__device__ __forceinline__ void cpa_wait0() {
    asm volatile("cp.async.wait_group 0;" ::: "memory");
}
__device__ __forceinline__ void ldsm4(uint32_t* r, uint32_t addr) {
    asm volatile("ldmatrix.sync.aligned.m8n8.x4.shared.b16 {%0,%1,%2,%3}, [%4];"
                 : "=r"(r[0]), "=r"(r[1]), "=r"(r[2]), "=r"(r[3]) : "r"(addr));
}
__device__ __forceinline__ void ldsm2(uint32_t* r, uint32_t addr) {
    asm volatile("ldmatrix.sync.aligned.m8n8.x2.shared.b16 {%0,%1}, [%2];"
                 : "=r"(r[0]), "=r"(r[1]) : "r"(addr));
}
__device__ __forceinline__ void mma16816(float* d, const uint32_t* a, const uint32_t* bq) {
    asm volatile(
        "mma.sync.aligned.m16n8k16.row.col.f32.f16.f16.f32 "
        "{%0,%1,%2,%3}, {%4,%5,%6,%7}, {%8,%9}, {%0,%1,%2,%3};"
        : "+f"(d[0]), "+f"(d[1]), "+f"(d[2]), "+f"(d[3])
        : "r"(a[0]), "r"(a[1]), "r"(a[2]), "r"(a[3]), "r"(bq[0]), "r"(bq[1]));
}

__global__ void __launch_bounds__(256, 1)
conv_mma_kernel(float* __restrict__ out) {
    extern __shared__ char smem[];
    uint32_t sb = smem_u32(smem);
    const int tid  = threadIdx.x;
    const int lane = tid & 31;
    const int wid  = tid >> 5;
    const int mw   = wid & 3;     // M quarter (64 voxels)
    const int nw   = wid >> 2;    // N half (72 co)

    const int d = blockIdx.y;
    const int b = blockIdx.z;
    const int n0 = blockIdx.x * 256;

    // ---- staging ----
    auto stageA = [&](int kd) {
        uint32_t base = sb + SM_A + (uint32_t)(kd & 1) * A_BYTES;
        const __half* src0 = g_xp + ((size_t)(b * 44 + d + kd) * NPLANE + n0) * 64;
        for (int i = tid; i < A_ROWS * 8; i += 256) {
            int r = i >> 3, c = i & 7;
            cpa16(base + r * 144 + c * 16, src0 + (size_t)r * 64 + c * 8);
        }
    };
    auto stageB = [&](int t) {
        uint32_t base = sb + SM_B + (uint32_t)(t & 3) * B_BYTES;
        const __half* src0 = g_wh + (size_t)t * 144 * 64;
        for (int i = tid; i < 144 * 8; i += 256) {
            int r = i >> 3, c = i & 7;
            cpa16(base + r * 144 + c * 16, src0 + (size_t)r * 64 + c * 8);
        }
    };

    // prologue: A(0) + B(0,1), full drain
    stageA(0);
    stageB(0); stageB(1);
    cpa_commit();
    cpa_wait0();
    __syncthreads();

    float acc[4][9][4];
#pragma unroll
    for (int mt = 0; mt < 4; mt++)
#pragma unroll
        for (int nt = 0; nt < 9; nt++)
#pragma unroll
            for (int q = 0; q < 4; q++) acc[mt][nt][q] = 0.f;

    const uint32_t aLaneOff = (uint32_t)((mw * 64 + (lane & 15)) * 144 + (lane >> 4) * 16);
    const uint32_t bOff4 = (uint32_t)((nw * 72 + ((lane >> 4) << 3) + (lane & 7)) * 144 +
                                      ((lane >> 3) & 1) * 16);
    const uint32_t bOff2 = (uint32_t)((nw * 72 + 64 + (lane & 7)) * 144 +
                                      ((lane >> 3) & 1) * 16);

    // fragment double buffers
    uint32_t aF[2][4][4];
    uint32_t bF[2][9][2];

    auto loadFrags = [&](uint32_t aTap, uint32_t bBase, int ks, int buf) {
#pragma unroll
        for (int mt = 0; mt < 4; mt++)
            ldsm4(aF[buf][mt], aTap + mt * (16 * 144) + ks * 32);
#pragma unroll
        for (int nt = 0; nt < 4; nt++) {
            uint32_t r4[4];
            ldsm4(r4, bBase + bOff4 + nt * (16 * 144) + ks * 32);
            bF[buf][2 * nt][0] = r4[0]; bF[buf][2 * nt][1] = r4[1];
            bF[buf][2 * nt + 1][0] = r4[2]; bF[buf][2 * nt + 1][1] = r4[3];
        }
        ldsm2(bF[buf][8], bBase + bOff2 + ks * 32);
    };
    auto tapAddr = [&](int t) -> uint32_t {
        int kd = t / 25, j = t - kd * 25;
        int kh = j / 5, kw = j - kh * 5;
        return sb + SM_A + (uint32_t)(kd & 1) * A_BYTES + aLaneOff +
               (uint32_t)((kh * WPLANE + kw) * 144);
    };
    auto bAddr = [&](int t) -> uint32_t {
        return sb + SM_B + (uint32_t)(t & 3) * B_BYTES;
    };

    // global windows of 2 taps: w=0..61 cover taps 0..123; w=62 is tap 124
#pragma unroll 1
    for (int w = 0; w < 63; w++) {
        const int t0 = 2 * w;
        const int ws = (t0 == 124) ? 1 : 2;

        if (t0 + 2 <= 124) stageB(t0 + 2);
        if (t0 + 3 <= 124) stageB(t0 + 3);
        if      (w == 0)  stageA(1);
        else if (w == 13) stageA(2);
        else if (w == 25) stageA(3);
        else if (w == 38) stageA(4);
        cpa_commit();

        uint32_t aTapC  = tapAddr(t0);
        uint32_t bBaseC = bAddr(t0);
        loadFrags(aTapC, bBaseC, 0, 0);
#pragma unroll 1
        for (int jj = 0; jj < ws; jj++) {
            int tn = t0 + jj + 1;
            uint32_t aTapN  = tapAddr(tn <= 124 ? tn : 124);
            uint32_t bBaseN = bAddr(tn);

#pragma unroll
            for (int ks = 0; ks < 4; ks++) {
                int cur = ks & 1, nxt = cur ^ 1;
                if (ks < 3)            loadFrags(aTapC, bBaseC, ks + 1, nxt);
                else if (jj + 1 < ws)  loadFrags(aTapN, bBaseN, 0, nxt);
#pragma unroll
                for (int mt = 0; mt < 4; mt++)
#pragma unroll
                    for (int nt = 0; nt < 9; nt++)
                        mma16816(acc[mt][nt], aF[cur][mt], bF[cur][nt]);
            }
            aTapC = aTapN; bBaseC = bBaseN;
        }

        cpa_wait0();
        __syncthreads();    // window boundary (final one frees smem for epilogue)
    }

    // ---- epilogue: stage acc to SMEM [co][m] then coalesced float4 stores ----
    float* sOut = (float*)smem;   // 144 * EPI_STRIDE * 4 = 149760 B <= SMEM_TOTAL
#pragma unroll
    for (int mt = 0; mt < 4; mt++) {
        int m0 = mw * 64 + mt * 16 + (lane >> 2);
#pragma unroll
        for (int nt = 0; nt < 9; nt++) {
            int co = nw * 72 + nt * 8 + (lane & 3) * 2;
            sOut[co * EPI_STRIDE + m0]            = acc[mt][nt][0];
            sOut[(co + 1) * EPI_STRIDE + m0]      = acc[mt][nt][1];
            sOut[co * EPI_STRIDE + m0 + 8]        = acc[mt][nt][2];
            sOut[(co + 1) * EPI_STRIDE + m0 + 8]  = acc[mt][nt][3];
        }
    }
    __syncthreads();

    const size_t ob = (size_t)b * 144 * 64000 + (size_t)d * 1600;
#pragma unroll 1
    for (int i = tid; i < 144 * 64; i += 256) {
        int co = i >> 6;
        int m  = (i & 63) * 4;
        int n  = n0 + m;
        int h  = n / WPLANE, w = n - h * WPLANE;   // w % 4 == 0
        if (w < 40 && n < NVALID) {
            float4 v = *(float4*)&sOut[co * EPI_STRIDE + m];
            *(float4*)&out[ob + (size_t)co * 64000 + h * 40 + w] = v;
        }
    }
}

// ===========================================================================
extern "C" void kernel_launch(void* const* d_in, const int* in_sizes, int n_in,
                              void* d_out, int out_size) {
    const float* x    = (const float*)d_in[0];
    const float* wsc0 = (const float*)d_in[1];
    const float* wsc1 = (const float*)d_in[2];
    const float* wtp  = (const float*)d_in[3];
    float* out = (float*)d_out;

    fill_xp_kernel<<<dim3(45, 44, 2), 256>>>(x);
    build_weights_kernel<<<125, 256>>>(wtp, wsc0, wsc1);

    cudaFuncSetAttribute(conv_mma_kernel,
                         cudaFuncAttributeMaxDynamicSharedMemorySize, SMEM_TOTAL);
    conv_mma_kernel<<<dim3(7, 40, 2), 256, SMEM_TOTAL>>>(out);
}